// round 1
// baseline (speedup 1.0000x reference)
#include <cuda_runtime.h>
#include <mma.h>
#include <cstdint>

using namespace nvcuda;

// Problem constants
#define BQ 4
#define LQ 8192
#define DQ 1024
#define NHQ 16
#define HDQ 64
#define MT (BQ * LQ)          // 32768 rows total
#define ROW_TILES (MT / 128)  // 256
#define COL_TILES (DQ / 128)  // 8

// ---------------- device scratch (no allocations allowed) ----------------
__device__ float g_Wv_sum[DQ * NHQ];     // [k][head] column-sums of Wv per head
__device__ float g_bv_sum[NHQ];
__device__ int   g_mask[MT];             // normalized 0/1 mask
__device__ int   g_mask_kind;            // 0=int32, 1=uint8, 2=float32
__device__ float g_partial[ROW_TILES * DQ]; // per-row-tile partial kv sums
__device__ float g_kv_sum[BQ * DQ];      // kv_sum[b][c], c = head*64 + k

__device__ __forceinline__ float phi_fn(float x) {
    // elu(x) + 1
    return x > 0.f ? x + 1.f : __expf(x);
}

__device__ __forceinline__ float to_tf32(float x) {
    return wmma::__float_to_tf32(x);
}

// ---------------- mask dtype detection + normalization ----------------
// The bool mask may be delivered as int32, uint8, or float32. Detect from the
// bit patterns of the first 32KB (safe to read for all three layouts).
__global__ void detect_mask_kernel(const unsigned int* m) {
    __shared__ int f_nonbin, f_float;
    if (threadIdx.x == 0) { f_nonbin = 0; f_float = 0; }
    __syncthreads();
    int nb = 0, fl = 0;
    for (int i = threadIdx.x; i < 8192; i += 256) {
        unsigned v = m[i];
        if (v == 0x3F800000u) fl = 1;      // 1.0f pattern -> float mask
        else if (v > 1u) nb = 1;           // packed bytes -> uint8 mask
    }
    if (fl) atomicOr(&f_float, 1);
    if (nb) atomicOr(&f_nonbin, 1);
    __syncthreads();
    if (threadIdx.x == 0) g_mask_kind = f_float ? 2 : (f_nonbin ? 1 : 0);
}

__global__ void normalize_mask_kernel(const void* m) {
    int i = blockIdx.x * 256 + threadIdx.x;
    if (i >= MT) return;
    int kind = g_mask_kind;
    int v;
    if (kind == 2)      v = (((const float*)m)[i] != 0.0f);
    else if (kind == 1) v = (((const unsigned char*)m)[i] != 0);
    else                v = (((const int*)m)[i] != 0);
    g_mask[i] = v;
}

// ---------------- Wv column sums per head (collapses V projection) ----------
__global__ void wvsum_kernel(const float* __restrict__ Wv,
                             const float* __restrict__ bv) {
    int t = blockIdx.x * 256 + threadIdx.x;
    if (t < DQ * NHQ) {
        int k = t >> 4, n = t & 15;
        const float* p = Wv + (size_t)k * DQ + n * HDQ;
        float s = 0.f;
        #pragma unroll 8
        for (int v = 0; v < HDQ; v++) s += p[v];
        g_Wv_sum[k * NHQ + n] = s;
    }
    if (t < NHQ) {
        const float* p = bv + t * HDQ;
        float s = 0.f;
        #pragma unroll 8
        for (int v = 0; v < HDQ; v++) s += p[v];
        g_bv_sum[t] = s;
    }
}

// ---------------- main GEMM: 128x128x16 tiles, tf32 wmma ----------------
// MODE 0: K projection. Epilogue: phi(K + bk) * sv, reduced over the 128 rows
//         of the tile -> g_partial[row_tile][col].  sv is computed on the fly
//         from the A-tile register staging (X @ Wv_sum), masked, + bv_sum.
// MODE 1: Q projection. Epilogue: out = phi(Q + bq) * kv_sum[b][col].
#define AS_LD 20
#define BS_LD 132
#define CT_LD 68
#define AS_OFF(buf) ((buf) * 128 * AS_LD)
#define BS_BASE (2 * 128 * AS_LD)                 // 5120 floats
#define BS_OFF(buf) (BS_BASE + (buf) * 16 * BS_LD)
#define SM_FLOATS (BS_BASE + 2 * 16 * BS_LD)      // 9344 floats (Ct 8704 fits)

__device__ __forceinline__ void sv_accum(const float4& a0, const float4& a1,
                                         int kb, int bn,
                                         float& s00, float& s01,
                                         float& s10, float& s11) {
    #pragma unroll
    for (int j = 0; j < 4; j++) {
        float av0 = (&a0.x)[j];
        float av1 = (&a1.x)[j];
        float2 w = *(const float2*)(g_Wv_sum + (kb + j) * NHQ + bn * 2);
        s00 += av0 * w.x; s01 += av0 * w.y;
        s10 += av1 * w.x; s11 += av1 * w.y;
    }
}

template <int MODE>
__global__ void __launch_bounds__(256)
gemm_kernel(const float* __restrict__ X, const float* __restrict__ W,
            const float* __restrict__ bias, float* __restrict__ outp) {
    __shared__ __align__(16) float sm[SM_FLOATS];
    __shared__ float svred[128 * 2];
    __shared__ float red2[256];

    const int tid = threadIdx.x;
    const int bn = blockIdx.x;   // column tile (128 cols = 2 heads)
    const int br = blockIdx.y;   // row tile (128 rows, within one batch)

    const float* Ab = X + (size_t)br * 128 * DQ;
    const float* Bb = W + bn * 128;

    // A staging: thread owns rows {ar, ar+64}, k-offset ac4*4..+3 of each stage
    const int ar = tid >> 2, ac4 = tid & 3;
    // B staging: thread owns rows {brr, brr+8}, col-offset bc4*4..+3
    const int brr = tid >> 5, bc4 = tid & 31;

    const int wid = tid >> 5;
    const int wm = wid & 3;       // warp row   (rows wm*32 .. +31)
    const int wn = wid >> 2;      // warp col   (cols wn*64 .. +63)

    wmma::fragment<wmma::accumulator, 16, 16, 8, float> fc[2][4];
    #pragma unroll
    for (int i = 0; i < 2; i++)
        #pragma unroll
        for (int j = 0; j < 4; j++)
            wmma::fill_fragment(fc[i][j], 0.f);

    // sv accumulators: rows {ar, ar+64} x heads {2*bn, 2*bn+1}
    float sv00 = 0.f, sv01 = 0.f, sv10 = 0.f, sv11 = 0.f;

    // ---- preload stage 0 ----
    {
        float4 a0 = *(const float4*)(Ab + (size_t)ar * DQ + ac4 * 4);
        float4 a1 = *(const float4*)(Ab + (size_t)(ar + 64) * DQ + ac4 * 4);
        float4 b0 = *(const float4*)(Bb + (size_t)brr * DQ + bc4 * 4);
        float4 b1 = *(const float4*)(Bb + (size_t)(brr + 8) * DQ + bc4 * 4);
        if (MODE == 0) sv_accum(a0, a1, ac4 * 4, bn, sv00, sv01, sv10, sv11);
        float* dA0 = &sm[AS_OFF(0) + ar * AS_LD + ac4 * 4];
        float* dA1 = &sm[AS_OFF(0) + (ar + 64) * AS_LD + ac4 * 4];
        float* dB0 = &sm[BS_OFF(0) + brr * BS_LD + bc4 * 4];
        float* dB1 = &sm[BS_OFF(0) + (brr + 8) * BS_LD + bc4 * 4];
        dA0[0] = to_tf32(a0.x); dA0[1] = to_tf32(a0.y); dA0[2] = to_tf32(a0.z); dA0[3] = to_tf32(a0.w);
        dA1[0] = to_tf32(a1.x); dA1[1] = to_tf32(a1.y); dA1[2] = to_tf32(a1.z); dA1[3] = to_tf32(a1.w);
        dB0[0] = to_tf32(b0.x); dB0[1] = to_tf32(b0.y); dB0[2] = to_tf32(b0.z); dB0[3] = to_tf32(b0.w);
        dB1[0] = to_tf32(b1.x); dB1[1] = to_tf32(b1.y); dB1[2] = to_tf32(b1.z); dB1[3] = to_tf32(b1.w);
    }
    __syncthreads();

    int buf = 0;
    const int NT = DQ / 16;   // 64 k-stages
    for (int t = 0; t < NT; t++) {
        float4 na0, na1, nb0, nb1;
        if (t < NT - 1) {
            int ko = (t + 1) * 16;
            na0 = *(const float4*)(Ab + (size_t)ar * DQ + ko + ac4 * 4);
            na1 = *(const float4*)(Ab + (size_t)(ar + 64) * DQ + ko + ac4 * 4);
            nb0 = *(const float4*)(Bb + (size_t)(ko + brr) * DQ + bc4 * 4);
            nb1 = *(const float4*)(Bb + (size_t)(ko + brr + 8) * DQ + bc4 * 4);
            if (MODE == 0) sv_accum(na0, na1, ko + ac4 * 4, bn, sv00, sv01, sv10, sv11);
        }

        // compute on smem[buf]
        #pragma unroll
        for (int kk = 0; kk < 2; kk++) {
            wmma::fragment<wmma::matrix_a, 16, 16, 8, wmma::precision::tf32, wmma::row_major> fa[2];
            wmma::fragment<wmma::matrix_b, 16, 16, 8, wmma::precision::tf32, wmma::row_major> fb[4];
            #pragma unroll
            for (int i = 0; i < 2; i++)
                wmma::load_matrix_sync(fa[i],
                    &sm[AS_OFF(buf) + (wm * 32 + i * 16) * AS_LD + kk * 8], AS_LD);
            #pragma unroll
            for (int j = 0; j < 4; j++)
                wmma::load_matrix_sync(fb[j],
                    &sm[BS_OFF(buf) + (kk * 8) * BS_LD + wn * 64 + j * 16], BS_LD);
            #pragma unroll
            for (int i = 0; i < 2; i++)
                #pragma unroll
                for (int j = 0; j < 4; j++)
                    wmma::mma_sync(fc[i][j], fa[i], fb[j], fc[i][j]);
        }

        if (t < NT - 1) {
            int nbuf = buf ^ 1;
            float* dA0 = &sm[AS_OFF(nbuf) + ar * AS_LD + ac4 * 4];
            float* dA1 = &sm[AS_OFF(nbuf) + (ar + 64) * AS_LD + ac4 * 4];
            float* dB0 = &sm[BS_OFF(nbuf) + brr * BS_LD + bc4 * 4];
            float* dB1 = &sm[BS_OFF(nbuf) + (brr + 8) * BS_LD + bc4 * 4];
            dA0[0] = to_tf32(na0.x); dA0[1] = to_tf32(na0.y); dA0[2] = to_tf32(na0.z); dA0[3] = to_tf32(na0.w);
            dA1[0] = to_tf32(na1.x); dA1[1] = to_tf32(na1.y); dA1[2] = to_tf32(na1.z); dA1[3] = to_tf32(na1.w);
            dB0[0] = to_tf32(nb0.x); dB0[1] = to_tf32(nb0.y); dB0[2] = to_tf32(nb0.z); dB0[3] = to_tf32(nb0.w);
            dB1[0] = to_tf32(nb1.x); dB1[1] = to_tf32(nb1.y); dB1[2] = to_tf32(nb1.z); dB1[3] = to_tf32(nb1.w);
        }
        __syncthreads();
        buf ^= 1;
    }

    if (MODE == 0) {
        // quad-reduce sv across the 4 threads (ac4=0..3) sharing each row
        #pragma unroll
        for (int off = 1; off <= 2; off <<= 1) {
            sv00 += __shfl_xor_sync(0xffffffffu, sv00, off);
            sv01 += __shfl_xor_sync(0xffffffffu, sv01, off);
            sv10 += __shfl_xor_sync(0xffffffffu, sv10, off);
            sv11 += __shfl_xor_sync(0xffffffffu, sv11, off);
        }
        if (ac4 == 0) {
            int grow = br * 128;
            int m0 = g_mask[grow + ar];
            int m1 = g_mask[grow + ar + 64];
            float bvs0 = g_bv_sum[bn * 2 + 0];
            float bvs1 = g_bv_sum[bn * 2 + 1];
            svred[ar * 2 + 0]        = m0 ? 0.f : sv00 + bvs0;
            svred[ar * 2 + 1]        = m0 ? 0.f : sv01 + bvs1;
            svred[(ar + 64) * 2 + 0] = m1 ? 0.f : sv10 + bvs0;
            svred[(ar + 64) * 2 + 1] = m1 ? 0.f : sv11 + bvs1;
        }
        #pragma unroll
        for (int hh = 0; hh < 2; hh++) {
            __syncthreads();
            if (wn == hh) {
                #pragma unroll
                for (int i = 0; i < 2; i++)
                    #pragma unroll
                    for (int j = 0; j < 4; j++)
                        wmma::store_matrix_sync(&sm[(wm * 32 + i * 16) * CT_LD + j * 16],
                                                fc[i][j], CT_LD, wmma::mem_row_major);
            }
            __syncthreads();
            int c = tid & 63, rg = tid >> 6;
            float bias_c = bias[bn * 128 + hh * 64 + c];
            float part = 0.f;
            #pragma unroll 8
            for (int r = rg; r < 128; r += 4) {
                float x = sm[r * CT_LD + c] + bias_c;
                part += phi_fn(x) * svred[r * 2 + hh];
            }
            red2[rg * 64 + c] = part;
            __syncthreads();
            if (tid < 64) {
                float tot = red2[tid] + red2[64 + tid] + red2[128 + tid] + red2[192 + tid];
                g_partial[(size_t)br * DQ + bn * 128 + hh * 64 + tid] = tot;
            }
        }
    } else {
        int b = br >> 6;   // 64 row tiles per batch
        #pragma unroll
        for (int hh = 0; hh < 2; hh++) {
            __syncthreads();
            if (wn == hh) {
                #pragma unroll
                for (int i = 0; i < 2; i++)
                    #pragma unroll
                    for (int j = 0; j < 4; j++)
                        wmma::store_matrix_sync(&sm[(wm * 32 + i * 16) * CT_LD + j * 16],
                                                fc[i][j], CT_LD, wmma::mem_row_major);
            }
            __syncthreads();
            int c = tid & 63, rg = tid >> 6;
            int gcol = bn * 128 + hh * 64 + c;
            float bias_c = bias[gcol];
            float kvs = g_kv_sum[b * DQ + gcol];
            #pragma unroll 8
            for (int r = rg; r < 128; r += 4) {
                float x = sm[r * CT_LD + c] + bias_c;
                outp[(size_t)(br * 128 + r) * DQ + gcol] = phi_fn(x) * kvs;
            }
        }
    }
}

// ---------------- deterministic reduction of per-tile partials ----------------
__global__ void kvreduce_kernel() {
    int t = blockIdx.x * 256 + threadIdx.x;
    if (t >= BQ * DQ) return;
    int b = t >> 10, c = t & 1023;
    const float* p = g_partial + (size_t)(b * 64) * DQ + c;
    float s = 0.f;
    #pragma unroll 8
    for (int j = 0; j < 64; j++) s += p[(size_t)j * DQ];
    g_kv_sum[t] = s;
}

// ---------------- entry point ----------------
extern "C" void kernel_launch(void* const* d_in, const int* in_sizes, int n_in,
                              void* d_out, int out_size) {
    const float* query = (const float*)d_in[0];
    const void*  mask  = d_in[1];
    const float* Wq    = (const float*)d_in[2];
    const float* bq    = (const float*)d_in[3];
    const float* Wk    = (const float*)d_in[4];
    const float* bk    = (const float*)d_in[5];
    const float* Wv    = (const float*)d_in[6];
    const float* bv    = (const float*)d_in[7];
    float* out = (float*)d_out;

    detect_mask_kernel<<<1, 256>>>((const unsigned int*)mask);
    normalize_mask_kernel<<<MT / 256, 256>>>(mask);
    wvsum_kernel<<<(DQ * NHQ + 255) / 256, 256>>>(Wv, bv);
    gemm_kernel<0><<<dim3(COL_TILES, ROW_TILES), 256>>>(query, Wk, bk, nullptr);
    kvreduce_kernel<<<(BQ * DQ + 255) / 256, 256>>>();
    gemm_kernel<1><<<dim3(COL_TILES, ROW_TILES), 256>>>(query, Wq, bq, out);
}

// round 4
// speedup vs baseline: 1.2013x; 1.2013x over previous
#include <cuda_runtime.h>
#include <mma.h>
#include <cstdint>

using namespace nvcuda;

// Problem constants
#define BQ 4
#define LQ 8192
#define DQ 1024
#define NHQ 16
#define HDQ 64
#define MT (BQ * LQ)          // 32768 rows total
#define ROW_TILES (MT / 128)  // 256
#define COL_TILES (DQ / 128)  // 8

// ---------------- device scratch (no allocations allowed) ----------------
__device__ __align__(16) float g_Wv_sum[DQ * NHQ];   // [k][head] column-sums of Wv
__device__ __align__(16) float g_bv_sum[NHQ];
__device__ __align__(16) int   g_mask[MT];
__device__ int   g_mask_kind;
__device__ __align__(16) float g_sv[MT * NHQ];       // masked row-sums of V
__device__ __align__(16) float g_partial[ROW_TILES * DQ];
__device__ __align__(16) float g_kv_sum[BQ * DQ];

__device__ __forceinline__ float phi_fn(float x) {
    return x > 0.f ? x + 1.f : __expf(x);   // elu(x)+1
}

__device__ __forceinline__ float to_tf32(float x) {
    return wmma::__float_to_tf32(x);
}

// ---------------- mask dtype detection + normalization ----------------
__global__ void detect_mask_kernel(const unsigned int* m) {
    __shared__ int f_nonbin, f_float;
    if (threadIdx.x == 0) { f_nonbin = 0; f_float = 0; }
    __syncthreads();
    int nb = 0, fl = 0;
    for (int i = threadIdx.x; i < 8192; i += 256) {
        unsigned v = m[i];
        if (v == 0x3F800000u) fl = 1;
        else if (v > 1u) nb = 1;
    }
    if (fl) atomicOr(&f_float, 1);
    if (nb) atomicOr(&f_nonbin, 1);
    __syncthreads();
    if (threadIdx.x == 0) g_mask_kind = f_float ? 2 : (f_nonbin ? 1 : 0);
}

__global__ void normalize_mask_kernel(const void* m) {
    int i = blockIdx.x * 256 + threadIdx.x;
    if (i >= MT) return;
    int kind = g_mask_kind;
    int v;
    if (kind == 2)      v = (((const float*)m)[i] != 0.0f);
    else if (kind == 1) v = (((const unsigned char*)m)[i] != 0);
    else                v = (((const int*)m)[i] != 0);
    g_mask[i] = v;
}

// ---------------- Wv column sums per head ----------------
__global__ void wvsum_kernel(const float* __restrict__ Wv,
                             const float* __restrict__ bv) {
    int t = blockIdx.x * 256 + threadIdx.x;
    if (t < DQ * NHQ) {
        int k = t >> 4, n = t & 15;
        const float* p = Wv + (size_t)k * DQ + n * HDQ;
        float s = 0.f;
        #pragma unroll 8
        for (int v = 0; v < HDQ; v++) s += p[v];
        g_Wv_sum[k * NHQ + n] = s;
    }
    if (t < NHQ) {
        const float* p = bv + t * HDQ;
        float s = 0.f;
        #pragma unroll 8
        for (int v = 0; v < HDQ; v++) s += p[v];
        g_bv_sum[t] = s;
    }
}

// ---------------- sv pre-pass: sv = mask ? 0 : X@Wv_sum + bv_sum ----------
// One warp per row, fp32 accuracy. (Hoisted out of the GEMM to free registers.)
__global__ void __launch_bounds__(256) sv_kernel(const float* __restrict__ X) {
    int warp = threadIdx.x >> 5, lane = threadIdx.x & 31;
    int row = blockIdx.x * 8 + warp;
    const float4* xr = (const float4*)(X + (size_t)row * DQ);
    float acc[NHQ];
    #pragma unroll
    for (int h = 0; h < NHQ; h++) acc[h] = 0.f;
    #pragma unroll 2
    for (int c = lane; c < DQ / 4; c += 32) {
        float4 v = xr[c];
        int k = c * 4;
        #pragma unroll
        for (int j = 0; j < 4; j++) {
            float xv = (&v.x)[j];
            const float4* wp = (const float4*)(g_Wv_sum + (size_t)(k + j) * NHQ);
            float4 w0 = wp[0], w1 = wp[1], w2 = wp[2], w3 = wp[3];
            acc[0]  += xv * w0.x; acc[1]  += xv * w0.y; acc[2]  += xv * w0.z; acc[3]  += xv * w0.w;
            acc[4]  += xv * w1.x; acc[5]  += xv * w1.y; acc[6]  += xv * w1.z; acc[7]  += xv * w1.w;
            acc[8]  += xv * w2.x; acc[9]  += xv * w2.y; acc[10] += xv * w2.z; acc[11] += xv * w2.w;
            acc[12] += xv * w3.x; acc[13] += xv * w3.y; acc[14] += xv * w3.z; acc[15] += xv * w3.w;
        }
    }
    #pragma unroll
    for (int off = 16; off; off >>= 1)
        #pragma unroll
        for (int h = 0; h < NHQ; h++)
            acc[h] += __shfl_xor_sync(0xffffffffu, acc[h], off);
    if (lane == 0) {
        int m = g_mask[row];
        #pragma unroll
        for (int h = 0; h < NHQ; h++)
            g_sv[(size_t)row * NHQ + h] = m ? 0.f : acc[h] + g_bv_sum[h];
    }
}

// ---------------- main GEMM: 128x128x16 tiles, tf32 wmma (round-1 core) ----
#define AS_LD 20
#define BS_LD 132
#define CT_LD 68
#define AS_OFF(buf) ((buf) * 128 * AS_LD)
#define BS_BASE (2 * 128 * AS_LD)                 // 5120 floats
#define BS_OFF(buf) (BS_BASE + (buf) * 16 * BS_LD)
#define SM_FLOATS (BS_BASE + 2 * 16 * BS_LD)      // 9344 floats (Ct 8704 fits)

template <int MODE>
__global__ void __launch_bounds__(256, 2)
gemm_kernel(const float* __restrict__ X, const float* __restrict__ W,
            const float* __restrict__ bias, float* __restrict__ outp) {
    __shared__ __align__(16) float sm[SM_FLOATS];
    __shared__ float svred[256];
    __shared__ float red2[256];

    const int tid = threadIdx.x;
    const int bn = blockIdx.x;   // column tile (128 cols = 2 heads)
    const int br = blockIdx.y;   // row tile (128 rows)

    const float* Ab = X + (size_t)br * 128 * DQ;
    const float* Bb = W + bn * 128;

    // A staging: thread owns rows {ar, ar+64}, k-offset ac4*4..+3 of each stage
    const int ar = tid >> 2, ac4 = tid & 3;
    // B staging: thread owns rows {brr, brr+8}, col-offset bc4*4..+3
    const int brr = tid >> 5, bc4 = tid & 31;

    const int wid = tid >> 5;
    const int wm = wid & 3;       // warp row   (rows wm*32 .. +31)
    const int wn = wid >> 2;      // warp col   (cols wn*64 .. +63)

    wmma::fragment<wmma::accumulator, 16, 16, 8, float> fc[2][4];
    #pragma unroll
    for (int i = 0; i < 2; i++)
        #pragma unroll
        for (int j = 0; j < 4; j++)
            wmma::fill_fragment(fc[i][j], 0.f);

    // ---- preload stage 0 ----
    {
        float4 a0 = *(const float4*)(Ab + (size_t)ar * DQ + ac4 * 4);
        float4 a1 = *(const float4*)(Ab + (size_t)(ar + 64) * DQ + ac4 * 4);
        float4 b0 = *(const float4*)(Bb + (size_t)brr * DQ + bc4 * 4);
        float4 b1 = *(const float4*)(Bb + (size_t)(brr + 8) * DQ + bc4 * 4);
        float* dA0 = &sm[AS_OFF(0) + ar * AS_LD + ac4 * 4];
        float* dA1 = &sm[AS_OFF(0) + (ar + 64) * AS_LD + ac4 * 4];
        float* dB0 = &sm[BS_OFF(0) + brr * BS_LD + bc4 * 4];
        float* dB1 = &sm[BS_OFF(0) + (brr + 8) * BS_LD + bc4 * 4];
        dA0[0] = to_tf32(a0.x); dA0[1] = to_tf32(a0.y); dA0[2] = to_tf32(a0.z); dA0[3] = to_tf32(a0.w);
        dA1[0] = to_tf32(a1.x); dA1[1] = to_tf32(a1.y); dA1[2] = to_tf32(a1.z); dA1[3] = to_tf32(a1.w);
        dB0[0] = to_tf32(b0.x); dB0[1] = to_tf32(b0.y); dB0[2] = to_tf32(b0.z); dB0[3] = to_tf32(b0.w);
        dB1[0] = to_tf32(b1.x); dB1[1] = to_tf32(b1.y); dB1[2] = to_tf32(b1.z); dB1[3] = to_tf32(b1.w);
    }
    __syncthreads();

    int buf = 0;
    const int NT = DQ / 16;   // 64 k-stages
    for (int t = 0; t < NT; t++) {
        float4 na0, na1, nb0, nb1;
        if (t < NT - 1) {
            int ko = (t + 1) * 16;
            na0 = *(const float4*)(Ab + (size_t)ar * DQ + ko + ac4 * 4);
            na1 = *(const float4*)(Ab + (size_t)(ar + 64) * DQ + ko + ac4 * 4);
            nb0 = *(const float4*)(Bb + (size_t)(ko + brr) * DQ + bc4 * 4);
            nb1 = *(const float4*)(Bb + (size_t)(ko + brr + 8) * DQ + bc4 * 4);
        }

        // compute on smem[buf]
        #pragma unroll
        for (int kk = 0; kk < 2; kk++) {
            wmma::fragment<wmma::matrix_a, 16, 16, 8, wmma::precision::tf32, wmma::row_major> fa[2];
            wmma::fragment<wmma::matrix_b, 16, 16, 8, wmma::precision::tf32, wmma::row_major> fb[4];
            #pragma unroll
            for (int i = 0; i < 2; i++)
                wmma::load_matrix_sync(fa[i],
                    &sm[AS_OFF(buf) + (wm * 32 + i * 16) * AS_LD + kk * 8], AS_LD);
            #pragma unroll
            for (int j = 0; j < 4; j++)
                wmma::load_matrix_sync(fb[j],
                    &sm[BS_OFF(buf) + (kk * 8) * BS_LD + wn * 64 + j * 16], BS_LD);
            #pragma unroll
            for (int i = 0; i < 2; i++)
                #pragma unroll
                for (int j = 0; j < 4; j++)
                    wmma::mma_sync(fc[i][j], fa[i], fb[j], fc[i][j]);
        }

        if (t < NT - 1) {
            int nbuf = buf ^ 1;
            float* dA0 = &sm[AS_OFF(nbuf) + ar * AS_LD + ac4 * 4];
            float* dA1 = &sm[AS_OFF(nbuf) + (ar + 64) * AS_LD + ac4 * 4];
            float* dB0 = &sm[BS_OFF(nbuf) + brr * BS_LD + bc4 * 4];
            float* dB1 = &sm[BS_OFF(nbuf) + (brr + 8) * BS_LD + bc4 * 4];
            dA0[0] = to_tf32(na0.x); dA0[1] = to_tf32(na0.y); dA0[2] = to_tf32(na0.z); dA0[3] = to_tf32(na0.w);
            dA1[0] = to_tf32(na1.x); dA1[1] = to_tf32(na1.y); dA1[2] = to_tf32(na1.z); dA1[3] = to_tf32(na1.w);
            dB0[0] = to_tf32(nb0.x); dB0[1] = to_tf32(nb0.y); dB0[2] = to_tf32(nb0.z); dB0[3] = to_tf32(nb0.w);
            dB1[0] = to_tf32(nb1.x); dB1[1] = to_tf32(nb1.y); dB1[2] = to_tf32(nb1.z); dB1[3] = to_tf32(nb1.w);
        }
        __syncthreads();
        buf ^= 1;
    }

    if (MODE == 0) {
        if (tid < 128) {
            float2 s = *(const float2*)(g_sv + (size_t)(br * 128 + tid) * NHQ + bn * 2);
            svred[tid * 2 + 0] = s.x;
            svred[tid * 2 + 1] = s.y;
        }
        #pragma unroll
        for (int hh = 0; hh < 2; hh++) {
            __syncthreads();
            if (wn == hh) {
                #pragma unroll
                for (int i = 0; i < 2; i++)
                    #pragma unroll
                    for (int j = 0; j < 4; j++)
                        wmma::store_matrix_sync(&sm[(wm * 32 + i * 16) * CT_LD + j * 16],
                                                fc[i][j], CT_LD, wmma::mem_row_major);
            }
            __syncthreads();
            int c = tid & 63, rg = tid >> 6;
            float bias_c = bias[bn * 128 + hh * 64 + c];
            float part = 0.f;
            #pragma unroll 8
            for (int r = rg; r < 128; r += 4) {
                float x = sm[r * CT_LD + c] + bias_c;
                part += phi_fn(x) * svred[r * 2 + hh];
            }
            red2[rg * 64 + c] = part;
            __syncthreads();
            if (tid < 64) {
                float tot = red2[tid] + red2[64 + tid] + red2[128 + tid] + red2[192 + tid];
                g_partial[(size_t)br * DQ + bn * 128 + hh * 64 + tid] = tot;
            }
        }
    } else {
        int b = br >> 6;   // 64 row tiles per batch
        #pragma unroll
        for (int hh = 0; hh < 2; hh++) {
            __syncthreads();
            if (wn == hh) {
                #pragma unroll
                for (int i = 0; i < 2; i++)
                    #pragma unroll
                    for (int j = 0; j < 4; j++)
                        wmma::store_matrix_sync(&sm[(wm * 32 + i * 16) * CT_LD + j * 16],
                                                fc[i][j], CT_LD, wmma::mem_row_major);
            }
            __syncthreads();
            int c = tid & 63, rg = tid >> 6;
            int gcol = bn * 128 + hh * 64 + c;
            float bias_c = bias[gcol];
            float kvs = g_kv_sum[b * DQ + gcol];
            #pragma unroll 8
            for (int r = rg; r < 128; r += 4) {
                float x = sm[r * CT_LD + c] + bias_c;
                outp[(size_t)(br * 128 + r) * DQ + gcol] = phi_fn(x) * kvs;
            }
        }
    }
}

// ---------------- deterministic reduction of per-tile partials ----------------
__global__ void kvreduce_kernel() {
    int t = blockIdx.x * 256 + threadIdx.x;
    if (t >= BQ * DQ) return;
    int b = t >> 10, c = t & 1023;
    const float* p = g_partial + (size_t)(b * 64) * DQ + c;
    float s = 0.f;
    #pragma unroll 8
    for (int j = 0; j < 64; j++) s += p[(size_t)j * DQ];
    g_kv_sum[t] = s;
}

// ---------------- entry point ----------------
extern "C" void kernel_launch(void* const* d_in, const int* in_sizes, int n_in,
                              void* d_out, int out_size) {
    const float* query = (const float*)d_in[0];
    const void*  mask  = d_in[1];
    const float* Wq    = (const float*)d_in[2];
    const float* bq    = (const float*)d_in[3];
    const float* Wk    = (const float*)d_in[4];
    const float* bk    = (const float*)d_in[5];
    const float* Wv    = (const float*)d_in[6];
    const float* bv    = (const float*)d_in[7];
    float* out = (float*)d_out;

    detect_mask_kernel<<<1, 256>>>((const unsigned int*)mask);
    normalize_mask_kernel<<<MT / 256, 256>>>(mask);
    wvsum_kernel<<<(DQ * NHQ + 255) / 256, 256>>>(Wv, bv);
    sv_kernel<<<MT / 8, 256>>>(query);
    gemm_kernel<0><<<dim3(COL_TILES, ROW_TILES), 256>>>(query, Wk, bk, nullptr);
    kvreduce_kernel<<<(BQ * DQ + 255) / 256, 256>>>();
    gemm_kernel<1><<<dim3(COL_TILES, ROW_TILES), 256>>>(query, Wq, bq, out);
}

// round 5
// speedup vs baseline: 1.4223x; 1.1840x over previous
#include <cuda_runtime.h>
#include <mma.h>
#include <cstdint>

using namespace nvcuda;

// Problem constants
#define BQ 4
#define LQ 8192
#define DQ 1024
#define NHQ 16
#define HDQ 64
#define MT (BQ * LQ)          // 32768 rows total
#define ROW_TILES (MT / 128)  // 256
#define COL_TILES (DQ / 128)  // 8

// ---------------- device scratch (no allocations allowed) ----------------
__device__ __align__(16) float g_Wv_sumT[NHQ * DQ];  // TRANSPOSED: [head][k]
__device__ __align__(16) float g_bv_sum[NHQ];
__device__ __align__(16) int   g_mask[MT];
__device__ int   g_mask_kind;
__device__ __align__(16) float g_sv[MT * NHQ];       // masked row-sums of V
__device__ __align__(16) float g_partial[ROW_TILES * DQ];
__device__ __align__(16) float g_kv_sum[BQ * DQ];

__device__ __forceinline__ float phi_fn(float x) {
    return x > 0.f ? x + 1.f : __expf(x);   // elu(x)+1
}

__device__ __forceinline__ float to_tf32(float x) {
    return wmma::__float_to_tf32(x);
}

// ---------------- mask dtype detection + normalization ----------------
__global__ void detect_mask_kernel(const unsigned int* m) {
    __shared__ int f_nonbin, f_float;
    if (threadIdx.x == 0) { f_nonbin = 0; f_float = 0; }
    __syncthreads();
    int nb = 0, fl = 0;
    for (int i = threadIdx.x; i < 8192; i += 256) {
        unsigned v = m[i];
        if (v == 0x3F800000u) fl = 1;
        else if (v > 1u) nb = 1;
    }
    if (fl) atomicOr(&f_float, 1);
    if (nb) atomicOr(&f_nonbin, 1);
    __syncthreads();
    if (threadIdx.x == 0) g_mask_kind = f_float ? 2 : (f_nonbin ? 1 : 0);
}

__global__ void normalize_mask_kernel(const void* m) {
    int i = blockIdx.x * 256 + threadIdx.x;
    if (i >= MT) return;
    int kind = g_mask_kind;
    int v;
    if (kind == 2)      v = (((const float*)m)[i] != 0.0f);
    else if (kind == 1) v = (((const unsigned char*)m)[i] != 0);
    else                v = (((const int*)m)[i] != 0);
    g_mask[i] = v;
}

// ---------------- Wv column sums per head (transposed output) ----------------
__global__ void wvsum_kernel(const float* __restrict__ Wv,
                             const float* __restrict__ bv) {
    int t = blockIdx.x * 256 + threadIdx.x;
    if (t < DQ * NHQ) {
        int k = t >> 4, n = t & 15;
        const float* p = Wv + (size_t)k * DQ + n * HDQ;
        float s = 0.f;
        #pragma unroll 8
        for (int v = 0; v < HDQ; v++) s += p[v];
        g_Wv_sumT[n * DQ + k] = s;        // transposed layout
    }
    if (t < NHQ) {
        const float* p = bv + t * HDQ;
        float s = 0.f;
        #pragma unroll 8
        for (int v = 0; v < HDQ; v++) s += p[v];
        g_bv_sum[t] = s;
    }
}

// ---------------- sv pre-pass: sv = mask ? 0 : X@Wv_sum + bv_sum ----------
// Wv_sumT staged once per block in 64KB dynamic smem; 4 rows per warp;
// one conflict-free LDS.128 feeds 16 FMAs.
__global__ void __launch_bounds__(256) sv_kernel(const float* __restrict__ X) {
    extern __shared__ __align__(16) float4 sWv[];   // [16][256] float4 = 64KB
    const int tid = threadIdx.x;
    {
        const float4* src = (const float4*)g_Wv_sumT;
        #pragma unroll
        for (int i = 0; i < NHQ * DQ / 4 / 256; i++)
            sWv[i * 256 + tid] = src[i * 256 + tid];
    }
    __syncthreads();

    const int warp = tid >> 5, lane = tid & 31;
    const int row0 = blockIdx.x * 32 + warp * 4;
    const float4* x0 = (const float4*)(X + (size_t)row0 * DQ);
    const float4* x1 = (const float4*)(X + (size_t)(row0 + 1) * DQ);
    const float4* x2 = (const float4*)(X + (size_t)(row0 + 2) * DQ);
    const float4* x3 = (const float4*)(X + (size_t)(row0 + 3) * DQ);

    float acc[4][NHQ];
    #pragma unroll
    for (int p = 0; p < 4; p++)
        #pragma unroll
        for (int h = 0; h < NHQ; h++) acc[p][h] = 0.f;

    for (int c = lane; c < DQ / 4; c += 32) {
        float4 xv0 = x0[c], xv1 = x1[c], xv2 = x2[c], xv3 = x3[c];
        #pragma unroll
        for (int h = 0; h < NHQ; h++) {
            float4 w = sWv[h * (DQ / 4) + c];
            acc[0][h] += xv0.x * w.x + xv0.y * w.y + xv0.z * w.z + xv0.w * w.w;
            acc[1][h] += xv1.x * w.x + xv1.y * w.y + xv1.z * w.z + xv1.w * w.w;
            acc[2][h] += xv2.x * w.x + xv2.y * w.y + xv2.z * w.z + xv2.w * w.w;
            acc[3][h] += xv3.x * w.x + xv3.y * w.y + xv3.z * w.z + xv3.w * w.w;
        }
    }
    // butterfly reduce across 32 lanes (all lanes end with full sums)
    #pragma unroll
    for (int off = 16; off; off >>= 1)
        #pragma unroll
        for (int p = 0; p < 4; p++)
            #pragma unroll
            for (int h = 0; h < NHQ; h++)
                acc[p][h] += __shfl_xor_sync(0xffffffffu, acc[p][h], off);
    // lanes 0..15 write head 'lane' for each of the 4 rows (coalesced 64B)
    if (lane < NHQ) {
        float bvs = g_bv_sum[lane];
        #pragma unroll
        for (int p = 0; p < 4; p++) {
            int m = g_mask[row0 + p];
            g_sv[(size_t)(row0 + p) * NHQ + lane] = m ? 0.f : acc[p][lane] + bvs;
        }
    }
}

// ---------------- main GEMM: 128x128x16 tiles, tf32 wmma (round-4 core) ----
#define AS_LD 20
#define BS_LD 132
#define CT_LD 68
#define AS_OFF(buf) ((buf) * 128 * AS_LD)
#define BS_BASE (2 * 128 * AS_LD)                 // 5120 floats
#define BS_OFF(buf) (BS_BASE + (buf) * 16 * BS_LD)
#define SM_FLOATS (BS_BASE + 2 * 16 * BS_LD)      // 9344 floats

template <int MODE>
__global__ void __launch_bounds__(256, 2)
gemm_kernel(const float* __restrict__ X, const float* __restrict__ W,
            const float* __restrict__ bias, float* __restrict__ outp) {
    __shared__ __align__(16) float sm[SM_FLOATS];
    __shared__ float svred[256];
    __shared__ float red2[256];

    const int tid = threadIdx.x;
    const int bn = blockIdx.x;   // column tile (128 cols = 2 heads)
    const int br = blockIdx.y;   // row tile (128 rows)

    const float* Ab = X + (size_t)br * 128 * DQ;
    const float* Bb = W + bn * 128;

    const int ar = tid >> 2, ac4 = tid & 3;
    const int brr = tid >> 5, bc4 = tid & 31;

    const int wid = tid >> 5;
    const int wm = wid & 3;       // warp row   (rows wm*32 .. +31)
    const int wn = wid >> 2;      // warp col   (cols wn*64 .. +63)

    wmma::fragment<wmma::accumulator, 16, 16, 8, float> fc[2][4];
    #pragma unroll
    for (int i = 0; i < 2; i++)
        #pragma unroll
        for (int j = 0; j < 4; j++)
            wmma::fill_fragment(fc[i][j], 0.f);

    // ---- preload stage 0 ----
    {
        float4 a0 = *(const float4*)(Ab + (size_t)ar * DQ + ac4 * 4);
        float4 a1 = *(const float4*)(Ab + (size_t)(ar + 64) * DQ + ac4 * 4);
        float4 b0 = *(const float4*)(Bb + (size_t)brr * DQ + bc4 * 4);
        float4 b1 = *(const float4*)(Bb + (size_t)(brr + 8) * DQ + bc4 * 4);
        float* dA0 = &sm[AS_OFF(0) + ar * AS_LD + ac4 * 4];
        float* dA1 = &sm[AS_OFF(0) + (ar + 64) * AS_LD + ac4 * 4];
        float* dB0 = &sm[BS_OFF(0) + brr * BS_LD + bc4 * 4];
        float* dB1 = &sm[BS_OFF(0) + (brr + 8) * BS_LD + bc4 * 4];
        dA0[0] = to_tf32(a0.x); dA0[1] = to_tf32(a0.y); dA0[2] = to_tf32(a0.z); dA0[3] = to_tf32(a0.w);
        dA1[0] = to_tf32(a1.x); dA1[1] = to_tf32(a1.y); dA1[2] = to_tf32(a1.z); dA1[3] = to_tf32(a1.w);
        dB0[0] = to_tf32(b0.x); dB0[1] = to_tf32(b0.y); dB0[2] = to_tf32(b0.z); dB0[3] = to_tf32(b0.w);
        dB1[0] = to_tf32(b1.x); dB1[1] = to_tf32(b1.y); dB1[2] = to_tf32(b1.z); dB1[3] = to_tf32(b1.w);
    }
    __syncthreads();

    int buf = 0;
    const int NT = DQ / 16;   // 64 k-stages
    for (int t = 0; t < NT; t++) {
        float4 na0, na1, nb0, nb1;
        if (t < NT - 1) {
            int ko = (t + 1) * 16;
            na0 = *(const float4*)(Ab + (size_t)ar * DQ + ko + ac4 * 4);
            na1 = *(const float4*)(Ab + (size_t)(ar + 64) * DQ + ko + ac4 * 4);
            nb0 = *(const float4*)(Bb + (size_t)(ko + brr) * DQ + bc4 * 4);
            nb1 = *(const float4*)(Bb + (size_t)(ko + brr + 8) * DQ + bc4 * 4);
        }

        #pragma unroll
        for (int kk = 0; kk < 2; kk++) {
            wmma::fragment<wmma::matrix_a, 16, 16, 8, wmma::precision::tf32, wmma::row_major> fa[2];
            wmma::fragment<wmma::matrix_b, 16, 16, 8, wmma::precision::tf32, wmma::row_major> fb[4];
            #pragma unroll
            for (int i = 0; i < 2; i++)
                wmma::load_matrix_sync(fa[i],
                    &sm[AS_OFF(buf) + (wm * 32 + i * 16) * AS_LD + kk * 8], AS_LD);
            #pragma unroll
            for (int j = 0; j < 4; j++)
                wmma::load_matrix_sync(fb[j],
                    &sm[BS_OFF(buf) + (kk * 8) * BS_LD + wn * 64 + j * 16], BS_LD);
            #pragma unroll
            for (int i = 0; i < 2; i++)
                #pragma unroll
                for (int j = 0; j < 4; j++)
                    wmma::mma_sync(fc[i][j], fa[i], fb[j], fc[i][j]);
        }

        if (t < NT - 1) {
            int nbuf = buf ^ 1;
            float* dA0 = &sm[AS_OFF(nbuf) + ar * AS_LD + ac4 * 4];
            float* dA1 = &sm[AS_OFF(nbuf) + (ar + 64) * AS_LD + ac4 * 4];
            float* dB0 = &sm[BS_OFF(nbuf) + brr * BS_LD + bc4 * 4];
            float* dB1 = &sm[BS_OFF(nbuf) + (brr + 8) * BS_LD + bc4 * 4];
            dA0[0] = to_tf32(na0.x); dA0[1] = to_tf32(na0.y); dA0[2] = to_tf32(na0.z); dA0[3] = to_tf32(na0.w);
            dA1[0] = to_tf32(na1.x); dA1[1] = to_tf32(na1.y); dA1[2] = to_tf32(na1.z); dA1[3] = to_tf32(na1.w);
            dB0[0] = to_tf32(nb0.x); dB0[1] = to_tf32(nb0.y); dB0[2] = to_tf32(nb0.z); dB0[3] = to_tf32(nb0.w);
            dB1[0] = to_tf32(nb1.x); dB1[1] = to_tf32(nb1.y); dB1[2] = to_tf32(nb1.z); dB1[3] = to_tf32(nb1.w);
        }
        __syncthreads();
        buf ^= 1;
    }

    if (MODE == 0) {
        if (tid < 128) {
            float2 s = *(const float2*)(g_sv + (size_t)(br * 128 + tid) * NHQ + bn * 2);
            svred[tid * 2 + 0] = s.x;
            svred[tid * 2 + 1] = s.y;
        }
        #pragma unroll
        for (int hh = 0; hh < 2; hh++) {
            __syncthreads();
            if (wn == hh) {
                #pragma unroll
                for (int i = 0; i < 2; i++)
                    #pragma unroll
                    for (int j = 0; j < 4; j++)
                        wmma::store_matrix_sync(&sm[(wm * 32 + i * 16) * CT_LD + j * 16],
                                                fc[i][j], CT_LD, wmma::mem_row_major);
            }
            __syncthreads();
            int c = tid & 63, rg = tid >> 6;
            float bias_c = bias[bn * 128 + hh * 64 + c];
            float part = 0.f;
            #pragma unroll 8
            for (int r = rg; r < 128; r += 4) {
                float x = sm[r * CT_LD + c] + bias_c;
                part += phi_fn(x) * svred[r * 2 + hh];
            }
            red2[rg * 64 + c] = part;
            __syncthreads();
            if (tid < 64) {
                float tot = red2[tid] + red2[64 + tid] + red2[128 + tid] + red2[192 + tid];
                g_partial[(size_t)br * DQ + bn * 128 + hh * 64 + tid] = tot;
            }
        }
    } else {
        int b = br >> 6;   // 64 row tiles per batch
        #pragma unroll
        for (int hh = 0; hh < 2; hh++) {
            __syncthreads();
            if (wn == hh) {
                #pragma unroll
                for (int i = 0; i < 2; i++)
                    #pragma unroll
                    for (int j = 0; j < 4; j++)
                        wmma::store_matrix_sync(&sm[(wm * 32 + i * 16) * CT_LD + j * 16],
                                                fc[i][j], CT_LD, wmma::mem_row_major);
            }
            __syncthreads();
            int c = tid & 63, rg = tid >> 6;
            int gcol = bn * 128 + hh * 64 + c;
            float bias_c = bias[gcol];
            float kvs = g_kv_sum[b * DQ + gcol];
            #pragma unroll 8
            for (int r = rg; r < 128; r += 4) {
                float x = sm[r * CT_LD + c] + bias_c;
                outp[(size_t)(br * 128 + r) * DQ + gcol] = phi_fn(x) * kvs;
            }
        }
    }
}

// ---------------- deterministic reduction of per-tile partials ----------------
__global__ void kvreduce_kernel() {
    int t = blockIdx.x * 256 + threadIdx.x;
    if (t >= BQ * DQ) return;
    int b = t >> 10, c = t & 1023;
    const float* p = g_partial + (size_t)(b * 64) * DQ + c;
    float s = 0.f;
    #pragma unroll 8
    for (int j = 0; j < 64; j++) s += p[(size_t)j * DQ];
    g_kv_sum[t] = s;
}

// ---------------- entry point ----------------
extern "C" void kernel_launch(void* const* d_in, const int* in_sizes, int n_in,
                              void* d_out, int out_size) {
    const float* query = (const float*)d_in[0];
    const void*  mask  = d_in[1];
    const float* Wq    = (const float*)d_in[2];
    const float* bq    = (const float*)d_in[3];
    const float* Wk    = (const float*)d_in[4];
    const float* bk    = (const float*)d_in[5];
    const float* Wv    = (const float*)d_in[6];
    const float* bv    = (const float*)d_in[7];
    float* out = (float*)d_out;

    const int sv_smem = NHQ * DQ * 4;   // 64KB dynamic smem for Wv_sumT
    cudaFuncSetAttribute(sv_kernel, cudaFuncAttributeMaxDynamicSharedMemorySize, sv_smem);

    detect_mask_kernel<<<1, 256>>>((const unsigned int*)mask);
    normalize_mask_kernel<<<MT / 256, 256>>>(mask);
    wvsum_kernel<<<(DQ * NHQ + 255) / 256, 256>>>(Wv, bv);
    sv_kernel<<<MT / 32, 256, sv_smem>>>(query);
    gemm_kernel<0><<<dim3(COL_TILES, ROW_TILES), 256>>>(query, Wk, bk, nullptr);
    kvreduce_kernel<<<(BQ * DQ + 255) / 256, 256>>>();
    gemm_kernel<1><<<dim3(COL_TILES, ROW_TILES), 256>>>(query, Wq, bq, out);
}